// round 14
// baseline (speedup 1.0000x reference)
#include <cuda_runtime.h>
#include <cuda_bf16.h>

#define BB 4
#define LL 1024
#define VV 1280
#define NE 768
#define NB 8
#define NH 32
#define NO 256          // NB*NH
#define NC 32           // chunks over L
#define CH 32           // chunk size (NC*CH == LL)

typedef unsigned long long ull;
typedef unsigned int u32;

// m16n8k16 row.col bf16 MMA, f32 accumulate-in-place
__device__ __forceinline__ void mma16816(float& d0, float& d1, float& d2, float& d3,
                                         uint4 a, uint2 b) {
    asm("mma.sync.aligned.m16n8k16.row.col.f32.bf16.bf16.f32 "
        "{%0,%1,%2,%3}, {%4,%5,%6,%7}, {%8,%9}, {%0,%1,%2,%3};"
        : "+f"(d0), "+f"(d1), "+f"(d2), "+f"(d3)
        : "r"(a.x), "r"(a.y), "r"(a.z), "r"(a.w), "r"(b.x), "r"(b.y));
}

// split a float2 into bf16x2 hi and lo words
__device__ __forceinline__ void split2(float2 p, u32& hi, u32& lo) {
    __nv_bfloat162 hb = __float22bfloat162_rn(p);
    float2 hf = __bfloat1622float2(hb);
    float2 lf = make_float2(p.x - hf.x, p.y - hf.y);
    __nv_bfloat162 lb = __float22bfloat162_rn(lf);
    hi = *(u32*)&hb;
    lo = *(u32*)&lb;
}

// Scratch (device globals: no allocation allowed)
__device__ int   g_chunk_first[BB * NC * VV];
__device__ int   g_next[BB * NC * VV];
// fragment buffers
#define NMT 256   // m-tiles (4096/16)
#define NKT 16    // k(col)-tiles of x (256/16)
#define NKT1 48   // k-tiles over NE (768/16)
__device__ uint4 g_xah[NMT * NKT * 32];
__device__ uint4 g_xal[NMT * NKT * 32];
__device__ uint4 g_hah[NMT * NKT1 * 32];
__device__ uint4 g_hal[NMT * NKT1 * 32];
#define NV8 160   // 1280/8
__device__ uint2 g_wbh[NV8 * 2 * 32];
__device__ uint2 g_wbl[NV8 * 2 * 32];
#define N81 32    // 256/8
__device__ uint2 g_w1bh[N81 * NKT1 * 32];
__device__ uint2 g_w1bl[N81 * NKT1 * 32];

#define W1FRAG (N81 * NKT1 * 32)    // 49152
#define W2FRAG (NV8 * 2 * 32)       // 10240
#define NWBLK  ((W1FRAG + W2FRAG + 255) / 256)   // 232
#define NHBLK  ((NMT * NKT1 * 32) / 256)          // 1536
#define NFOBLK (BB * NC)                           // 128

// ===========================================================================
// FUSED PREP: repack_w + repack_h + first_occ   (256 threads)
// ===========================================================================
__global__ __launch_bounds__(256) void fused_prep_kernel(
    const float* __restrict__ W1, const float* __restrict__ W2,
    const float* __restrict__ h, const int* __restrict__ targets)
{
    __shared__ int arr[VV];
    const int blk = blockIdx.x;
    const int tid = threadIdx.x;

    if (blk < NWBLK) {
        const int gt = blk * 256 + tid;
        const int l = gt & 31;
        const int g = l >> 2, t = l & 3;

        if (gt < W1FRAG) {
            const int kt = (gt >> 5) % NKT1;
            const int n8 = gt / (NKT1 * 32);
            const int o = n8 * 8 + g;
            const int k0 = kt * 16 + t * 2;

            float2 q0 = make_float2(W1[(k0 + 0) * NO + o], W1[(k0 + 1) * NO + o]);
            float2 q1 = make_float2(W1[(k0 + 8) * NO + o], W1[(k0 + 9) * NO + o]);

            uint2 hv, lv;
            split2(q0, hv.x, lv.x);
            split2(q1, hv.y, lv.y);
            g_w1bh[gt] = hv;
            g_w1bl[gt] = lv;
        } else {
            const int gw = gt - W1FRAG;
            if (gw >= W2FRAG) return;
            const int kt = (gw >> 5) & 1;
            const int v8 = gw >> 6;
            const int v = v8 * 8 + g;
            const int k0 = kt * 16 + t * 2;

            float2 q0 = make_float2(W2[(k0 + 0) * VV + v], W2[(k0 + 1) * VV + v]);
            float2 q1 = make_float2(W2[(k0 + 8) * VV + v], W2[(k0 + 9) * VV + v]);

            uint2 hv, lv;
            split2(q0, hv.x, lv.x);
            split2(q1, hv.y, lv.y);
            g_wbh[gw] = hv;
            g_wbl[gw] = lv;
        }
    } else if (blk < NWBLK + NHBLK) {
        const int gt = (blk - NWBLK) * 256 + tid;
        const int l = gt & 31;
        const int kt = (gt >> 5) % NKT1;
        const int mt = gt / (NKT1 * 32);
        const int g = l >> 2, t = l & 3;

        const int r0 = mt * 16 + g, r1 = r0 + 8;
        const int ca = kt * 16 + t * 2, cb = ca + 8;

        float2 p00 = *(const float2*)&h[r0 * NE + ca];
        float2 p10 = *(const float2*)&h[r1 * NE + ca];
        float2 p01 = *(const float2*)&h[r0 * NE + cb];
        float2 p11 = *(const float2*)&h[r1 * NE + cb];

        uint4 hv, lv;
        split2(p00, hv.x, lv.x);
        split2(p10, hv.y, lv.y);
        split2(p01, hv.z, lv.z);
        split2(p11, hv.w, lv.w);
        g_hah[gt] = hv;
        g_hal[gt] = lv;
    } else {
        const int fb = blk - NWBLK - NHBLK;
        const int b = fb >> 5;
        const int c = fb & 31;

#pragma unroll
        for (int it = 0; it < 5; ++it) arr[tid + it * 256] = LL;
        __syncthreads();
        if (tid < CH) {
            int j = c * CH + tid;
            atomicMin(&arr[targets[b * LL + j]], j);
        }
        __syncthreads();
#pragma unroll
        for (int it = 0; it < 5; ++it) {
            int idx = tid + it * 256;
            g_chunk_first[(b * NC + c) * VV + idx] = arr[idx];
        }
    }
}

// ===========================================================================
// FUSED MID: gemm1_mma (256 blocks) + suffix (40 blocks)   (128 threads)
// ===========================================================================
__global__ __launch_bounds__(128) void fused_mid_kernel()
{
    const int blk = blockIdx.x;

    if (blk < 256) {
        const int w = threadIdx.x >> 5;
        const int l = threadIdx.x & 31;
        const int mw = w & 1;
        const int nw = w >> 1;
        const int mt0 = (blk >> 2) * 4 + mw * 2;
        const int kto0 = (blk & 3) * 4 + nw * 2;
        const int n80 = kto0 * 2;

        float acc[2][4][4];
#pragma unroll
        for (int mi = 0; mi < 2; ++mi)
#pragma unroll
            for (int i = 0; i < 4; ++i)
#pragma unroll
                for (int q = 0; q < 4; ++q) acc[mi][i][q] = 0.0f;

        uint4 Ah[2][2], Al[2][2];
        uint2 Bh[2][4], Bl[2][4];

#define LOAD_A(kt, buf) do { \
    _Pragma("unroll") \
    for (int mi = 0; mi < 2; ++mi) { \
        int idx = ((mt0 + mi) * NKT1 + (kt)) * 32 + l; \
        Ah[buf][mi] = g_hah[idx]; Al[buf][mi] = g_hal[idx]; \
    } } while (0)
#define LOAD_B(kt, buf) do { \
    _Pragma("unroll") \
    for (int i = 0; i < 4; ++i) { \
        int idx = ((n80 + i) * NKT1 + (kt)) * 32 + l; \
        Bh[buf][i] = g_w1bh[idx]; Bl[buf][i] = g_w1bl[idx]; \
    } } while (0)
#define DO_MMA(buf) do { \
    _Pragma("unroll") \
    for (int mi = 0; mi < 2; ++mi) \
    _Pragma("unroll") \
    for (int i = 0; i < 4; ++i) { \
        float* d = acc[mi][i]; \
        mma16816(d[0], d[1], d[2], d[3], Ah[buf][mi], Bh[buf][i]); \
        mma16816(d[0], d[1], d[2], d[3], Ah[buf][mi], Bl[buf][i]); \
        mma16816(d[0], d[1], d[2], d[3], Al[buf][mi], Bh[buf][i]); \
    } } while (0)

        LOAD_A(0, 0); LOAD_B(0, 0);
#pragma unroll 1
        for (int kt = 0; kt < NKT1; kt += 2) {
            LOAD_A(kt + 1, 1); LOAD_B(kt + 1, 1);
            DO_MMA(0);
            if (kt + 2 < NKT1) { LOAD_A(kt + 2, 0); LOAD_B(kt + 2, 0); }
            DO_MMA(1);
        }
#undef LOAD_A
#undef LOAD_B
#undef DO_MMA

#pragma unroll
        for (int mi = 0; mi < 2; ++mi)
#pragma unroll
            for (int kto = 0; kto < 2; ++kto) {
                const float* da = acc[mi][kto * 2 + 0];
                const float* db = acc[mi][kto * 2 + 1];
                uint4 hv, lv;
                split2(make_float2(da[0], da[1]), hv.x, lv.x);
                split2(make_float2(da[2], da[3]), hv.y, lv.y);
                split2(make_float2(db[0], db[1]), hv.z, lv.z);
                split2(make_float2(db[2], db[3]), hv.w, lv.w);
                int idx = ((mt0 + mi) * NKT + (kto0 + kto)) * 32 + l;
                g_xah[idx] = hv;
                g_xal[idx] = lv;
            }
    } else {
        const int gt = (blk - 256) * 128 + threadIdx.x;   // 0..5119
        if (gt >= BB * VV) return;
        const int b = gt / VV;
        const int v = gt - b * VV;

        int cf[NC];
#pragma unroll
        for (int c = 0; c < NC; ++c) cf[c] = g_chunk_first[(b * NC + c) * VV + v];

        int run = LL;
#pragma unroll
        for (int c = NC - 1; c >= 0; --c) {
            g_next[(b * NC + c) * VV + v] = run;
            run = min(run, cf[c]);
        }
    }
}

// ===========================================================================
// FUSED MAIN: gemm2_mma (2560 blocks; warp = 1 m-tile x 4 v8, bin loop
// double-buffered with LITERAL buffer indices) + tte_mask (256 blocks),
// interleaved every 11th block.   (160 threads; gemm2 uses tid<128)
// ===========================================================================
#define NG2BLK 2560
__global__ __launch_bounds__(160) void fused_main_kernel(
    const int* __restrict__ targets,
    const float* __restrict__ age,
    const float* __restrict__ targets_age,
    float* __restrict__ logits,
    float* __restrict__ out_tte,
    float* __restrict__ out_mask)
{
    __shared__ float ta_s[LL];
    __shared__ int ts[CH];
    __shared__ float ag[CH];

    const int blk = blockIdx.x;          // 0..2815
    const int tq = blk / 11;
    const int rq = blk - tq * 11;

    if (rq != 0) {
        // ---- gemm2_mma, pipelined. idx2 = tq*10 + rq-1 in 0..2559 ----
        if (threadIdx.x >= 128) return;
        const int idx2 = tq * 10 + (rq - 1);
        const int bx = idx2 % 40;            // v block of 32
        const int rest = idx2 / 40;          // 0..63 : group of 4 m-tiles

        const int w = threadIdx.x >> 5;
        const int l = threadIdx.x & 31;
        const int g = l >> 2, t = l & 3;
        const int mt = rest * 4 + w;         // this warp's m-tile

        // B fragments (bin-invariant)
        uint2 Bh[4][2], Bl[4][2];
#pragma unroll
        for (int v8i = 0; v8i < 4; ++v8i)
#pragma unroll
            for (int j = 0; j < 2; ++j) {
                int idx = (((bx * 4 + v8i) * 2 + j) * 32) + l;
                Bh[v8i][j] = g_wbh[idx];
                Bl[v8i][j] = g_wbl[idx];
            }

        uint4 Ah[2][2], Al[2][2];            // [buf][j]
        const int abase = mt * NKT * 32 + l;

#define G2_LOAD(n, buf) do { \
    _Pragma("unroll") \
    for (int j = 0; j < 2; ++j) { \
        int idx = abase + (2 * (n) + j) * 32; \
        Ah[buf][j] = g_xah[idx]; Al[buf][j] = g_xal[idx]; \
    } } while (0)
#define G2_CS(n, buf) do { \
    float acc[4][4]; \
    _Pragma("unroll") \
    for (int v8i = 0; v8i < 4; ++v8i) \
    _Pragma("unroll") \
        for (int q = 0; q < 4; ++q) acc[v8i][q] = 0.0f; \
    _Pragma("unroll") \
    for (int v8i = 0; v8i < 4; ++v8i) \
    _Pragma("unroll") \
        for (int j = 0; j < 2; ++j) { \
            float* d = acc[v8i]; \
            mma16816(d[0], d[1], d[2], d[3], Ah[buf][j], Bh[v8i][j]); \
            mma16816(d[0], d[1], d[2], d[3], Ah[buf][j], Bl[v8i][j]); \
            mma16816(d[0], d[1], d[2], d[3], Al[buf][j], Bh[v8i][j]); \
        } \
    const int mlo = mt * 16 + g; \
    _Pragma("unroll") \
    for (int v8i = 0; v8i < 4; ++v8i) { \
        const int v = (bx * 4 + v8i) * 8 + t * 2; \
        float* d = acc[v8i]; \
        *(float2*)&logits[((mlo + 0) * NB + (n)) * VV + v] = make_float2(d[0], d[1]); \
        *(float2*)&logits[((mlo + 8) * NB + (n)) * VV + v] = make_float2(d[2], d[3]); \
    } } while (0)

        G2_LOAD(0, 0);
#pragma unroll 1
        for (int n = 0; n < NB; n += 2) {
            G2_LOAD(n + 1, 1);
            G2_CS(n, 0);
            if (n + 2 < NB) G2_LOAD(n + 2, 0);
            G2_CS(n + 1, 1);
        }
#undef G2_LOAD
#undef G2_CS
    } else {
        // ---- tte_mask (byte-identical body); block index = tq (0..255) ----
        const int b = tq >> 6;
        const int rem = tq & 63;
        const int c = rem >> 1;
        const int half = rem & 1;
        const int tid = threadIdx.x;        // 0..159

        for (int idx = tid; idx < LL; idx += 160)
            ta_s[idx] = targets_age[b * LL + idx];
        if (tid < CH) {
            int i = c * CH + tid;
            ts[tid] = targets[b * LL + i];
            ag[tid] = age[b * LL + i];
        }
        __syncthreads();

        const int vb = half * 640 + tid * 4;
        int4 c4 = *(const int4*)&g_next[(b * NC + c) * VV + vb];
        int cur0 = c4.x, cur1 = c4.y, cur2 = c4.z, cur3 = c4.w;

        for (int jj = CH - 1; jj >= 0; --jj) {
            const int i = c * CH + jj;
            const int t = ts[jj];
            const float ai = ag[jj];

            if (t == vb + 0) cur0 = i;
            if (t == vb + 1) cur1 = i;
            if (t == vb + 2) cur2 = i;
            if (t == vb + 3) cur3 = i;

            float tte[4];
            bool nev[4];
            int curs[4] = {cur0, cur1, cur2, cur3};
#pragma unroll
            for (int q = 0; q < 4; ++q) {
                int vv = vb + q;
                int idxr = curs[q];
                if (vv == 0 && i > 0) idxr = 0;  // reference's where(upper,...) quirk
                bool ne = (idxr == LL);
                int idx = ne ? (LL - 1) : idxr;
                tte[q] = ta_s[idx] - ai;
                nev[q] = ne;
            }

            const int row = b * LL + i;
            *(float4*)&out_tte[row * VV + vb] = make_float4(tte[0], tte[1], tte[2], tte[3]);

            int bin[4];
            bool valid[4];
#pragma unroll
            for (int q = 0; q < 4; ++q) {
                float tq2 = tte[q];
                valid[q] = (tq2 >= 0.0f) && (tq2 < 10.0f);
                bin[q] = (tq2 >= 1.25f) + (tq2 >= 2.5f) + (tq2 >= 3.75f) + (tq2 >= 5.0f)
                       + (tq2 >= 6.25f) + (tq2 >= 7.5f) + (tq2 >= 8.75f);
            }

            const int mbase = row * NB * VV + vb;
#pragma unroll
            for (int n = 0; n < 8; ++n) {
                float4 mv;
                mv.x = (nev[0] || (valid[0] && bin[0] == n)) ? 1.0f : 0.0f;
                mv.y = (nev[1] || (valid[1] && bin[1] == n)) ? 1.0f : 0.0f;
                mv.z = (nev[2] || (valid[2] && bin[2] == n)) ? 1.0f : 0.0f;
                mv.w = (nev[3] || (valid[3] && bin[3] == n)) ? 1.0f : 0.0f;
                *(float4*)&out_mask[mbase + n * VV] = mv;
            }
        }
    }
}

// ---------------------------------------------------------------------------
extern "C" void kernel_launch(void* const* d_in, const int* in_sizes, int n_in,
                              void* d_out, int out_size)
{
    const float* h   = (const float*)d_in[0];  // (B,L,768) f32
    const float* age = (const float*)d_in[1];  // (B,L) f32
    const float* ta  = (const float*)d_in[2];  // (B,L) f32 targets_age
    // d_in[3] = delta_t (unused by outputs)
    const int*   tg  = (const int*)d_in[4];    // (B,L) i32 targets
    const float* W1  = (const float*)d_in[5];  // (768,256) f32
    const float* W2  = (const float*)d_in[6];  // (32,1280) f32

    float* out = (float*)d_out;
    float* out_logits = out;                                  // B*L*8*V
    float* out_tte    = out + (size_t)BB * LL * NB * VV;      // B*L*V
    float* out_mask   = out_tte + (size_t)BB * LL * VV;       // B*L*8*V

    fused_prep_kernel<<<NWBLK + NHBLK + NFOBLK, 256>>>(W1, W2, h, tg);
    fused_mid_kernel<<<256 + 40, 128>>>();
    fused_main_kernel<<<NG2BLK + 256, 160>>>(tg, age, ta, out_logits, out_tte, out_mask);
}

// round 15
// speedup vs baseline: 1.0263x; 1.0263x over previous
#include <cuda_runtime.h>
#include <cuda_bf16.h>

#define BB 4
#define LL 1024
#define VV 1280
#define NE 768
#define NB 8
#define NH 32
#define NO 256          // NB*NH
#define NC 32           // chunks over L
#define CH 32           // chunk size (NC*CH == LL)

typedef unsigned long long ull;
typedef unsigned int u32;

// m16n8k16 row.col bf16 MMA, f32 accumulate-in-place
__device__ __forceinline__ void mma16816(float& d0, float& d1, float& d2, float& d3,
                                         uint4 a, uint2 b) {
    asm("mma.sync.aligned.m16n8k16.row.col.f32.bf16.bf16.f32 "
        "{%0,%1,%2,%3}, {%4,%5,%6,%7}, {%8,%9}, {%0,%1,%2,%3};"
        : "+f"(d0), "+f"(d1), "+f"(d2), "+f"(d3)
        : "r"(a.x), "r"(a.y), "r"(a.z), "r"(a.w), "r"(b.x), "r"(b.y));
}

// split a float2 into bf16x2 hi and lo words
__device__ __forceinline__ void split2(float2 p, u32& hi, u32& lo) {
    __nv_bfloat162 hb = __float22bfloat162_rn(p);
    float2 hf = __bfloat1622float2(hb);
    float2 lf = make_float2(p.x - hf.x, p.y - hf.y);
    __nv_bfloat162 lb = __float22bfloat162_rn(lf);
    hi = *(u32*)&hb;
    lo = *(u32*)&lb;
}

// Scratch (device globals: no allocation allowed)
__device__ int   g_next[BB * NC * VV];
// fragment buffers
#define NMT 256   // m-tiles (4096/16)
#define NKT 16    // k(col)-tiles of x (256/16)
#define NKT1 48   // k-tiles over NE (768/16)
__device__ uint4 g_xah[NMT * NKT * 32];
__device__ uint4 g_xal[NMT * NKT * 32];
__device__ uint4 g_hah[NMT * NKT1 * 32];
__device__ uint4 g_hal[NMT * NKT1 * 32];
#define NV8 160   // 1280/8
__device__ uint2 g_wbh[NV8 * 2 * 32];
__device__ uint2 g_wbl[NV8 * 2 * 32];
#define N81 32    // 256/8
__device__ uint2 g_w1bh[N81 * NKT1 * 32];
__device__ uint2 g_w1bl[N81 * NKT1 * 32];

#define W1FRAG (N81 * NKT1 * 32)    // 49152
#define W2FRAG (NV8 * 2 * 32)       // 10240
#define NSCAN  (BB * 5)                            // 20 scan blocks (256 v each)
#define NWBLK  ((W1FRAG + W2FRAG + 255) / 256)    // 232
#define NHBLK  ((NMT * NKT1 * 32) / 256)           // 1536

// ===========================================================================
// K1: scan(first_occ+suffix fused) + repack_w + repack_h   (256 threads)
// Scan blocks placed FIRST (longest-latency singletons start earliest).
// ===========================================================================
__global__ __launch_bounds__(256) void fused_prep_kernel(
    const float* __restrict__ W1, const float* __restrict__ W2,
    const float* __restrict__ h, const int* __restrict__ targets)
{
    __shared__ int ts_s[LL];
    const int blk = blockIdx.x;
    const int tid = threadIdx.x;

    if (blk < NSCAN) {
        // ---- fused first_occ + suffix: backward scan per (b, v) ----
        // g_next[b][c][v] = min index i of v among chunks c' > c, else LL.
        const int b = blk / 5;
        const int v = (blk % 5) * 256 + tid;

        for (int i = tid; i < LL; i += 256)
            ts_s[i] = targets[b * LL + i];
        __syncthreads();

        int run = LL;
#pragma unroll 1
        for (int c = NC - 1; c >= 0; --c) {
            g_next[(b * NC + c) * VV + v] = run;   // exclusive: chunks > c only
#pragma unroll
            for (int j = CH - 1; j >= 0; --j) {
                int i = c * CH + j;
                if (ts_s[i] == v) run = i;          // descending -> min index
            }
        }
    } else if (blk < NSCAN + NWBLK) {
        // ---- repack_w (byte-identical body) ----
        const int gt = (blk - NSCAN) * 256 + tid;
        const int l = gt & 31;
        const int g = l >> 2, t = l & 3;

        if (gt < W1FRAG) {
            const int kt = (gt >> 5) % NKT1;
            const int n8 = gt / (NKT1 * 32);
            const int o = n8 * 8 + g;
            const int k0 = kt * 16 + t * 2;

            float2 q0 = make_float2(W1[(k0 + 0) * NO + o], W1[(k0 + 1) * NO + o]);
            float2 q1 = make_float2(W1[(k0 + 8) * NO + o], W1[(k0 + 9) * NO + o]);

            uint2 hv, lv;
            split2(q0, hv.x, lv.x);
            split2(q1, hv.y, lv.y);
            g_w1bh[gt] = hv;
            g_w1bl[gt] = lv;
        } else {
            const int gw = gt - W1FRAG;
            if (gw >= W2FRAG) return;
            const int kt = (gw >> 5) & 1;
            const int v8 = gw >> 6;
            const int v = v8 * 8 + g;
            const int k0 = kt * 16 + t * 2;

            float2 q0 = make_float2(W2[(k0 + 0) * VV + v], W2[(k0 + 1) * VV + v]);
            float2 q1 = make_float2(W2[(k0 + 8) * VV + v], W2[(k0 + 9) * VV + v]);

            uint2 hv, lv;
            split2(q0, hv.x, lv.x);
            split2(q1, hv.y, lv.y);
            g_wbh[gw] = hv;
            g_wbl[gw] = lv;
        }
    } else {
        // ---- repack_h (byte-identical body) ----
        const int gt = (blk - NSCAN - NWBLK) * 256 + tid;
        const int l = gt & 31;
        const int kt = (gt >> 5) % NKT1;
        const int mt = gt / (NKT1 * 32);
        const int g = l >> 2, t = l & 3;

        const int r0 = mt * 16 + g, r1 = r0 + 8;
        const int ca = kt * 16 + t * 2, cb = ca + 8;

        float2 p00 = *(const float2*)&h[r0 * NE + ca];
        float2 p10 = *(const float2*)&h[r1 * NE + ca];
        float2 p01 = *(const float2*)&h[r0 * NE + cb];
        float2 p11 = *(const float2*)&h[r1 * NE + cb];

        uint4 hv, lv;
        split2(p00, hv.x, lv.x);
        split2(p10, hv.y, lv.y);
        split2(p01, hv.z, lv.z);
        split2(p11, hv.w, lv.w);
        g_hah[gt] = hv;
        g_hal[gt] = lv;
    }
}

// ===========================================================================
// K2: gemm1_mma (256 blocks) + tte_mask (256 blocks), interleaved 1:1.
// 160 threads; gemm1 path uses tid<128 (bodies byte-identical).
// gemm1 is tensor/latency-bound, tte_mask is store-bound -> complementary.
// ===========================================================================
__global__ __launch_bounds__(160) void fused_g1_tte_kernel(
    const int* __restrict__ targets,
    const float* __restrict__ age,
    const float* __restrict__ targets_age,
    float* __restrict__ out_tte,
    float* __restrict__ out_mask)
{
    __shared__ float ta_s[LL];
    __shared__ int ts[CH];
    __shared__ float ag[CH];

    const int blk = blockIdx.x;          // 0..511

    if ((blk & 1) == 0) {
        // ---- gemm1_mma (byte-identical); g1 = blk>>1 in 0..255 ----
        if (threadIdx.x >= 128) return;
        const int g1 = blk >> 1;
        const int w = threadIdx.x >> 5;
        const int l = threadIdx.x & 31;
        const int mw = w & 1;
        const int nw = w >> 1;
        const int mt0 = (g1 >> 2) * 4 + mw * 2;
        const int kto0 = (g1 & 3) * 4 + nw * 2;
        const int n80 = kto0 * 2;

        float acc[2][4][4];
#pragma unroll
        for (int mi = 0; mi < 2; ++mi)
#pragma unroll
            for (int i = 0; i < 4; ++i)
#pragma unroll
                for (int q = 0; q < 4; ++q) acc[mi][i][q] = 0.0f;

        uint4 Ah[2][2], Al[2][2];
        uint2 Bh[2][4], Bl[2][4];

#define LOAD_A(kt, buf) do { \
    _Pragma("unroll") \
    for (int mi = 0; mi < 2; ++mi) { \
        int idx = ((mt0 + mi) * NKT1 + (kt)) * 32 + l; \
        Ah[buf][mi] = g_hah[idx]; Al[buf][mi] = g_hal[idx]; \
    } } while (0)
#define LOAD_B(kt, buf) do { \
    _Pragma("unroll") \
    for (int i = 0; i < 4; ++i) { \
        int idx = ((n80 + i) * NKT1 + (kt)) * 32 + l; \
        Bh[buf][i] = g_w1bh[idx]; Bl[buf][i] = g_w1bl[idx]; \
    } } while (0)
#define DO_MMA(buf) do { \
    _Pragma("unroll") \
    for (int mi = 0; mi < 2; ++mi) \
    _Pragma("unroll") \
    for (int i = 0; i < 4; ++i) { \
        float* d = acc[mi][i]; \
        mma16816(d[0], d[1], d[2], d[3], Ah[buf][mi], Bh[buf][i]); \
        mma16816(d[0], d[1], d[2], d[3], Ah[buf][mi], Bl[buf][i]); \
        mma16816(d[0], d[1], d[2], d[3], Al[buf][mi], Bh[buf][i]); \
    } } while (0)

        LOAD_A(0, 0); LOAD_B(0, 0);
#pragma unroll 1
        for (int kt = 0; kt < NKT1; kt += 2) {
            LOAD_A(kt + 1, 1); LOAD_B(kt + 1, 1);
            DO_MMA(0);
            if (kt + 2 < NKT1) { LOAD_A(kt + 2, 0); LOAD_B(kt + 2, 0); }
            DO_MMA(1);
        }
#undef LOAD_A
#undef LOAD_B
#undef DO_MMA

#pragma unroll
        for (int mi = 0; mi < 2; ++mi)
#pragma unroll
            for (int kto = 0; kto < 2; ++kto) {
                const float* da = acc[mi][kto * 2 + 0];
                const float* db = acc[mi][kto * 2 + 1];
                uint4 hv, lv;
                split2(make_float2(da[0], da[1]), hv.x, lv.x);
                split2(make_float2(da[2], da[3]), hv.y, lv.y);
                split2(make_float2(db[0], db[1]), hv.z, lv.z);
                split2(make_float2(db[2], db[3]), hv.w, lv.w);
                int idx = ((mt0 + mi) * NKT + (kto0 + kto)) * 32 + l;
                g_xah[idx] = hv;
                g_xal[idx] = lv;
            }
    } else {
        // ---- tte_mask (byte-identical); tq = blk>>1 in 0..255 ----
        const int tq = blk >> 1;
        const int b = tq >> 6;
        const int rem = tq & 63;
        const int c = rem >> 1;
        const int half = rem & 1;
        const int tid = threadIdx.x;        // 0..159

        for (int idx = tid; idx < LL; idx += 160)
            ta_s[idx] = targets_age[b * LL + idx];
        if (tid < CH) {
            int i = c * CH + tid;
            ts[tid] = targets[b * LL + i];
            ag[tid] = age[b * LL + i];
        }
        __syncthreads();

        const int vb = half * 640 + tid * 4;
        int4 c4 = *(const int4*)&g_next[(b * NC + c) * VV + vb];
        int cur0 = c4.x, cur1 = c4.y, cur2 = c4.z, cur3 = c4.w;

        for (int jj = CH - 1; jj >= 0; --jj) {
            const int i = c * CH + jj;
            const int t = ts[jj];
            const float ai = ag[jj];

            if (t == vb + 0) cur0 = i;
            if (t == vb + 1) cur1 = i;
            if (t == vb + 2) cur2 = i;
            if (t == vb + 3) cur3 = i;

            float tte[4];
            bool nev[4];
            int curs[4] = {cur0, cur1, cur2, cur3};
#pragma unroll
            for (int q = 0; q < 4; ++q) {
                int vv = vb + q;
                int idxr = curs[q];
                if (vv == 0 && i > 0) idxr = 0;  // reference's where(upper,...) quirk
                bool ne = (idxr == LL);
                int idx = ne ? (LL - 1) : idxr;
                tte[q] = ta_s[idx] - ai;
                nev[q] = ne;
            }

            const int row = b * LL + i;
            *(float4*)&out_tte[row * VV + vb] = make_float4(tte[0], tte[1], tte[2], tte[3]);

            int bin[4];
            bool valid[4];
#pragma unroll
            for (int q = 0; q < 4; ++q) {
                float tq2 = tte[q];
                valid[q] = (tq2 >= 0.0f) && (tq2 < 10.0f);
                bin[q] = (tq2 >= 1.25f) + (tq2 >= 2.5f) + (tq2 >= 3.75f) + (tq2 >= 5.0f)
                       + (tq2 >= 6.25f) + (tq2 >= 7.5f) + (tq2 >= 8.75f);
            }

            const int mbase = row * NB * VV + vb;
#pragma unroll
            for (int n = 0; n < 8; ++n) {
                float4 mv;
                mv.x = (nev[0] || (valid[0] && bin[0] == n)) ? 1.0f : 0.0f;
                mv.y = (nev[1] || (valid[1] && bin[1] == n)) ? 1.0f : 0.0f;
                mv.z = (nev[2] || (valid[2] && bin[2] == n)) ? 1.0f : 0.0f;
                mv.w = (nev[3] || (valid[3] && bin[3] == n)) ? 1.0f : 0.0f;
                *(float4*)&out_mask[mbase + n * VV] = mv;
            }
        }
    }
}

// ===========================================================================
// K3: gemm2_mma standalone — exact R12 verified body (44.1us measured).
// ===========================================================================
__global__ __launch_bounds__(128) void gemm2_mma_kernel(float* __restrict__ logits)
{
    const int w = threadIdx.x >> 5;
    const int l = threadIdx.x & 31;
    const int g = l >> 2, t = l & 3;
    const int bx = blockIdx.x;          // 0..39 : v block of 32
    const int by = blockIdx.y;          // 0..31 : m block of 128
    const int mt0 = by * 8 + w * 2;

    uint2 Bh[4][2], Bl[4][2];
#pragma unroll
    for (int v8i = 0; v8i < 4; ++v8i)
#pragma unroll
        for (int j = 0; j < 2; ++j) {
            int idx = (((bx * 4 + v8i) * 2 + j) * 32) + l;
            Bh[v8i][j] = g_wbh[idx];
            Bl[v8i][j] = g_wbl[idx];
        }

#pragma unroll
    for (int n = 0; n < NB; ++n) {
        uint4 Ah[2][2], Al[2][2];
#pragma unroll
        for (int mi = 0; mi < 2; ++mi)
#pragma unroll
            for (int j = 0; j < 2; ++j) {
                int idx = (((mt0 + mi) * NKT + (2 * n + j)) * 32) + l;
                Ah[mi][j] = g_xah[idx];
                Al[mi][j] = g_xal[idx];
            }

        float acc[2][4][4];
#pragma unroll
        for (int mi = 0; mi < 2; ++mi)
#pragma unroll
            for (int v8i = 0; v8i < 4; ++v8i)
#pragma unroll
                for (int q = 0; q < 4; ++q) acc[mi][v8i][q] = 0.0f;

#pragma unroll
        for (int mi = 0; mi < 2; ++mi)
#pragma unroll
            for (int v8i = 0; v8i < 4; ++v8i)
#pragma unroll
                for (int j = 0; j < 2; ++j) {
                    float* d = acc[mi][v8i];
                    mma16816(d[0], d[1], d[2], d[3], Ah[mi][j], Bh[v8i][j]);
                    mma16816(d[0], d[1], d[2], d[3], Ah[mi][j], Bl[v8i][j]);
                    mma16816(d[0], d[1], d[2], d[3], Al[mi][j], Bh[v8i][j]);
                }

#pragma unroll
        for (int mi = 0; mi < 2; ++mi) {
            const int mlo = (mt0 + mi) * 16 + g;
#pragma unroll
            for (int v8i = 0; v8i < 4; ++v8i) {
                const int v = (bx * 4 + v8i) * 8 + t * 2;
                float* d = acc[mi][v8i];
                *(float2*)&logits[((mlo + 0) * NB + n) * VV + v] = make_float2(d[0], d[1]);
                *(float2*)&logits[((mlo + 8) * NB + n) * VV + v] = make_float2(d[2], d[3]);
            }
        }
    }
}

// ---------------------------------------------------------------------------
extern "C" void kernel_launch(void* const* d_in, const int* in_sizes, int n_in,
                              void* d_out, int out_size)
{
    const float* h   = (const float*)d_in[0];  // (B,L,768) f32
    const float* age = (const float*)d_in[1];  // (B,L) f32
    const float* ta  = (const float*)d_in[2];  // (B,L) f32 targets_age
    // d_in[3] = delta_t (unused by outputs)
    const int*   tg  = (const int*)d_in[4];    // (B,L) i32 targets
    const float* W1  = (const float*)d_in[5];  // (768,256) f32
    const float* W2  = (const float*)d_in[6];  // (32,1280) f32

    float* out = (float*)d_out;
    float* out_logits = out;                                  // B*L*8*V
    float* out_tte    = out + (size_t)BB * LL * NB * VV;      // B*L*V
    float* out_mask   = out_tte + (size_t)BB * LL * VV;       // B*L*8*V

    fused_prep_kernel<<<NSCAN + NWBLK + NHBLK, 256>>>(W1, W2, h, tg);
    fused_g1_tte_kernel<<<512, 160>>>(tg, age, ta, out_tte, out_mask);
    gemm2_mma_kernel<<<dim3(VV / 32, (BB * LL) / 128), 128>>>(out_logits);
}

// round 16
// speedup vs baseline: 1.2208x; 1.1895x over previous
#include <cuda_runtime.h>
#include <cuda_bf16.h>

#define BB 4
#define LL 1024
#define VV 1280
#define NE 768
#define NB 8
#define NH 32
#define NO 256          // NB*NH
#define NC 64           // chunks over L (finer for tte grid)
#define CH 16           // chunk size (NC*CH == LL)

typedef unsigned long long ull;
typedef unsigned int u32;

// m16n8k16 row.col bf16 MMA, f32 accumulate-in-place
__device__ __forceinline__ void mma16816(float& d0, float& d1, float& d2, float& d3,
                                         uint4 a, uint2 b) {
    asm("mma.sync.aligned.m16n8k16.row.col.f32.bf16.bf16.f32 "
        "{%0,%1,%2,%3}, {%4,%5,%6,%7}, {%8,%9}, {%0,%1,%2,%3};"
        : "+f"(d0), "+f"(d1), "+f"(d2), "+f"(d3)
        : "r"(a.x), "r"(a.y), "r"(a.z), "r"(a.w), "r"(b.x), "r"(b.y));
}

// split a float2 into bf16x2 hi and lo words
__device__ __forceinline__ void split2(float2 p, u32& hi, u32& lo) {
    __nv_bfloat162 hb = __float22bfloat162_rn(p);
    float2 hf = __bfloat1622float2(hb);
    float2 lf = make_float2(p.x - hf.x, p.y - hf.y);
    __nv_bfloat162 lb = __float22bfloat162_rn(lf);
    hi = *(u32*)&hb;
    lo = *(u32*)&lb;
}

// evict-first (streaming) output stores — outputs are never re-read
__device__ __forceinline__ void st_cs_f2(float* p, float a, float b) {
    asm volatile("st.global.cs.v2.f32 [%0], {%1, %2};"
                 :: "l"(p), "f"(a), "f"(b) : "memory");
}
__device__ __forceinline__ void st_cs_f4(float* p, float4 v) {
    asm volatile("st.global.cs.v4.f32 [%0], {%1, %2, %3, %4};"
                 :: "l"(p), "f"(v.x), "f"(v.y), "f"(v.z), "f"(v.w) : "memory");
}

// Scratch (device globals: no allocation allowed)
__device__ int   g_next[BB * NC * VV];         // 1.3 MB
// fragment buffers
#define NMT 256   // m-tiles (4096/16)
#define NKT 16    // k(col)-tiles of x (256/16)
#define NKT1 48   // k-tiles over NE (768/16)
__device__ uint4 g_xah[NMT * NKT * 32];
__device__ uint4 g_xal[NMT * NKT * 32];
__device__ uint4 g_hah[NMT * NKT1 * 32];
__device__ uint4 g_hal[NMT * NKT1 * 32];
#define NV8 160   // 1280/8
__device__ uint2 g_wbh[NV8 * 2 * 32];
__device__ uint2 g_wbl[NV8 * 2 * 32];
#define N81 32    // 256/8
__device__ uint2 g_w1bh[N81 * NKT1 * 32];
__device__ uint2 g_w1bl[N81 * NKT1 * 32];

#define W1FRAG (N81 * NKT1 * 32)    // 49152
#define W2FRAG (NV8 * 2 * 32)       // 10240
#define NSCAN  (BB * 5)                            // 20 scan blocks (256 v each)
#define NWBLK  ((W1FRAG + W2FRAG + 255) / 256)    // 232
#define NHBLK  ((NMT * NKT1 * 32) / 256)           // 1536

// ===========================================================================
// K1: scan(first_occ+suffix fused, NC=64) + repack_w + repack_h (256 threads)
// ===========================================================================
__global__ __launch_bounds__(256) void fused_prep_kernel(
    const float* __restrict__ W1, const float* __restrict__ W2,
    const float* __restrict__ h, const int* __restrict__ targets)
{
    __shared__ int ts_s[LL];
    const int blk = blockIdx.x;
    const int tid = threadIdx.x;

    if (blk < NSCAN) {
        // ---- fused first_occ + suffix: backward scan per (b, v) ----
        const int b = blk / 5;
        const int v = (blk % 5) * 256 + tid;

        for (int i = tid; i < LL; i += 256)
            ts_s[i] = targets[b * LL + i];
        __syncthreads();

        int run = LL;
#pragma unroll 1
        for (int c = NC - 1; c >= 0; --c) {
            g_next[(b * NC + c) * VV + v] = run;   // exclusive: chunks > c only
#pragma unroll
            for (int j = CH - 1; j >= 0; --j) {
                int i = c * CH + j;
                if (ts_s[i] == v) run = i;          // descending -> min index
            }
        }
    } else if (blk < NSCAN + NWBLK) {
        // ---- repack_w (byte-identical body) ----
        const int gt = (blk - NSCAN) * 256 + tid;
        const int l = gt & 31;
        const int g = l >> 2, t = l & 3;

        if (gt < W1FRAG) {
            const int kt = (gt >> 5) % NKT1;
            const int n8 = gt / (NKT1 * 32);
            const int o = n8 * 8 + g;
            const int k0 = kt * 16 + t * 2;

            float2 q0 = make_float2(W1[(k0 + 0) * NO + o], W1[(k0 + 1) * NO + o]);
            float2 q1 = make_float2(W1[(k0 + 8) * NO + o], W1[(k0 + 9) * NO + o]);

            uint2 hv, lv;
            split2(q0, hv.x, lv.x);
            split2(q1, hv.y, lv.y);
            g_w1bh[gt] = hv;
            g_w1bl[gt] = lv;
        } else {
            const int gw = gt - W1FRAG;
            if (gw >= W2FRAG) return;
            const int kt = (gw >> 5) & 1;
            const int v8 = gw >> 6;
            const int v = v8 * 8 + g;
            const int k0 = kt * 16 + t * 2;

            float2 q0 = make_float2(W2[(k0 + 0) * VV + v], W2[(k0 + 1) * VV + v]);
            float2 q1 = make_float2(W2[(k0 + 8) * VV + v], W2[(k0 + 9) * VV + v]);

            uint2 hv, lv;
            split2(q0, hv.x, lv.x);
            split2(q1, hv.y, lv.y);
            g_wbh[gw] = hv;
            g_wbl[gw] = lv;
        }
    } else {
        // ---- repack_h (byte-identical body) ----
        const int gt = (blk - NSCAN - NWBLK) * 256 + tid;
        const int l = gt & 31;
        const int kt = (gt >> 5) % NKT1;
        const int mt = gt / (NKT1 * 32);
        const int g = l >> 2, t = l & 3;

        const int r0 = mt * 16 + g, r1 = r0 + 8;
        const int ca = kt * 16 + t * 2, cb = ca + 8;

        float2 p00 = *(const float2*)&h[r0 * NE + ca];
        float2 p10 = *(const float2*)&h[r1 * NE + ca];
        float2 p01 = *(const float2*)&h[r0 * NE + cb];
        float2 p11 = *(const float2*)&h[r1 * NE + cb];

        uint4 hv, lv;
        split2(p00, hv.x, lv.x);
        split2(p10, hv.y, lv.y);
        split2(p01, hv.z, lv.z);
        split2(p11, hv.w, lv.w);
        g_hah[gt] = hv;
        g_hal[gt] = lv;
    }
}

// ===========================================================================
// K2: gemm1_mma (blocks 0..255) then tte_mask (blocks 256..767).
// gemm1 first fills the initial wave; store-bound tte streams behind it.
// 160 threads; gemm1 path uses tid<128 (bodies byte-identical).
// ===========================================================================
__global__ __launch_bounds__(160) void fused_g1_tte_kernel(
    const int* __restrict__ targets,
    const float* __restrict__ age,
    const float* __restrict__ targets_age,
    float* __restrict__ out_tte,
    float* __restrict__ out_mask)
{
    __shared__ float ta_s[LL];
    __shared__ int ts[CH];
    __shared__ float ag[CH];

    const int blk = blockIdx.x;          // 0..767

    if (blk < 256) {
        // ---- gemm1_mma (byte-identical); g1 = blk ----
        if (threadIdx.x >= 128) return;
        const int g1 = blk;
        const int w = threadIdx.x >> 5;
        const int l = threadIdx.x & 31;
        const int mw = w & 1;
        const int nw = w >> 1;
        const int mt0 = (g1 >> 2) * 4 + mw * 2;
        const int kto0 = (g1 & 3) * 4 + nw * 2;
        const int n80 = kto0 * 2;

        float acc[2][4][4];
#pragma unroll
        for (int mi = 0; mi < 2; ++mi)
#pragma unroll
            for (int i = 0; i < 4; ++i)
#pragma unroll
                for (int q = 0; q < 4; ++q) acc[mi][i][q] = 0.0f;

        uint4 Ah[2][2], Al[2][2];
        uint2 Bh[2][4], Bl[2][4];

#define LOAD_A(kt, buf) do { \
    _Pragma("unroll") \
    for (int mi = 0; mi < 2; ++mi) { \
        int idx = ((mt0 + mi) * NKT1 + (kt)) * 32 + l; \
        Ah[buf][mi] = g_hah[idx]; Al[buf][mi] = g_hal[idx]; \
    } } while (0)
#define LOAD_B(kt, buf) do { \
    _Pragma("unroll") \
    for (int i = 0; i < 4; ++i) { \
        int idx = ((n80 + i) * NKT1 + (kt)) * 32 + l; \
        Bh[buf][i] = g_w1bh[idx]; Bl[buf][i] = g_w1bl[idx]; \
    } } while (0)
#define DO_MMA(buf) do { \
    _Pragma("unroll") \
    for (int mi = 0; mi < 2; ++mi) \
    _Pragma("unroll") \
    for (int i = 0; i < 4; ++i) { \
        float* d = acc[mi][i]; \
        mma16816(d[0], d[1], d[2], d[3], Ah[buf][mi], Bh[buf][i]); \
        mma16816(d[0], d[1], d[2], d[3], Ah[buf][mi], Bl[buf][i]); \
        mma16816(d[0], d[1], d[2], d[3], Al[buf][mi], Bh[buf][i]); \
    } } while (0)

        LOAD_A(0, 0); LOAD_B(0, 0);
#pragma unroll 1
        for (int kt = 0; kt < NKT1; kt += 2) {
            LOAD_A(kt + 1, 1); LOAD_B(kt + 1, 1);
            DO_MMA(0);
            if (kt + 2 < NKT1) { LOAD_A(kt + 2, 0); LOAD_B(kt + 2, 0); }
            DO_MMA(1);
        }
#undef LOAD_A
#undef LOAD_B
#undef DO_MMA

#pragma unroll
        for (int mi = 0; mi < 2; ++mi)
#pragma unroll
            for (int kto = 0; kto < 2; ++kto) {
                const float* da = acc[mi][kto * 2 + 0];
                const float* db = acc[mi][kto * 2 + 1];
                uint4 hv, lv;
                split2(make_float2(da[0], da[1]), hv.x, lv.x);
                split2(make_float2(da[2], da[3]), hv.y, lv.y);
                split2(make_float2(db[0], db[1]), hv.z, lv.z);
                split2(make_float2(db[2], db[3]), hv.w, lv.w);
                int idx = ((mt0 + mi) * NKT + (kto0 + kto)) * 32 + l;
                g_xah[idx] = hv;
                g_xal[idx] = lv;
            }
    } else {
        // ---- tte_mask; tq = blk-256 in 0..511 (NC=64, CH=16) ----
        const int tq = blk - 256;
        const int b = tq >> 7;
        const int rem = tq & 127;
        const int c = rem >> 1;
        const int half = rem & 1;
        const int tid = threadIdx.x;        // 0..159

        for (int idx = tid; idx < LL; idx += 160)
            ta_s[idx] = targets_age[b * LL + idx];
        if (tid < CH) {
            int i = c * CH + tid;
            ts[tid] = targets[b * LL + i];
            ag[tid] = age[b * LL + i];
        }
        __syncthreads();

        const int vb = half * 640 + tid * 4;
        int4 c4 = *(const int4*)&g_next[(b * NC + c) * VV + vb];
        int cur0 = c4.x, cur1 = c4.y, cur2 = c4.z, cur3 = c4.w;

        for (int jj = CH - 1; jj >= 0; --jj) {
            const int i = c * CH + jj;
            const int t = ts[jj];
            const float ai = ag[jj];

            if (t == vb + 0) cur0 = i;
            if (t == vb + 1) cur1 = i;
            if (t == vb + 2) cur2 = i;
            if (t == vb + 3) cur3 = i;

            float tte[4];
            bool nev[4];
            int curs[4] = {cur0, cur1, cur2, cur3};
#pragma unroll
            for (int q = 0; q < 4; ++q) {
                int vv = vb + q;
                int idxr = curs[q];
                if (vv == 0 && i > 0) idxr = 0;  // reference's where(upper,...) quirk
                bool ne = (idxr == LL);
                int idx = ne ? (LL - 1) : idxr;
                tte[q] = ta_s[idx] - ai;
                nev[q] = ne;
            }

            const int row = b * LL + i;
            st_cs_f4(&out_tte[row * VV + vb], make_float4(tte[0], tte[1], tte[2], tte[3]));

            int bin[4];
            bool valid[4];
#pragma unroll
            for (int q = 0; q < 4; ++q) {
                float tq2 = tte[q];
                valid[q] = (tq2 >= 0.0f) && (tq2 < 10.0f);
                bin[q] = (tq2 >= 1.25f) + (tq2 >= 2.5f) + (tq2 >= 3.75f) + (tq2 >= 5.0f)
                       + (tq2 >= 6.25f) + (tq2 >= 7.5f) + (tq2 >= 8.75f);
            }

            const int mbase = row * NB * VV + vb;
#pragma unroll
            for (int n = 0; n < 8; ++n) {
                float4 mv;
                mv.x = (nev[0] || (valid[0] && bin[0] == n)) ? 1.0f : 0.0f;
                mv.y = (nev[1] || (valid[1] && bin[1] == n)) ? 1.0f : 0.0f;
                mv.z = (nev[2] || (valid[2] && bin[2] == n)) ? 1.0f : 0.0f;
                mv.w = (nev[3] || (valid[3] && bin[3] == n)) ? 1.0f : 0.0f;
                st_cs_f4(&out_mask[mbase + n * VV], mv);
            }
        }
    }
}

// ===========================================================================
// K3: gemm2_mma standalone — exact R12 verified body, stores via st.global.cs.
// ===========================================================================
__global__ __launch_bounds__(128) void gemm2_mma_kernel(float* __restrict__ logits)
{
    const int w = threadIdx.x >> 5;
    const int l = threadIdx.x & 31;
    const int g = l >> 2, t = l & 3;
    const int bx = blockIdx.x;          // 0..39 : v block of 32
    const int by = blockIdx.y;          // 0..31 : m block of 128
    const int mt0 = by * 8 + w * 2;

    uint2 Bh[4][2], Bl[4][2];
#pragma unroll
    for (int v8i = 0; v8i < 4; ++v8i)
#pragma unroll
        for (int j = 0; j < 2; ++j) {
            int idx = (((bx * 4 + v8i) * 2 + j) * 32) + l;
            Bh[v8i][j] = g_wbh[idx];
            Bl[v8i][j] = g_wbl[idx];
        }

#pragma unroll
    for (int n = 0; n < NB; ++n) {
        uint4 Ah[2][2], Al[2][2];
#pragma unroll
        for (int mi = 0; mi < 2; ++mi)
#pragma unroll
            for (int j = 0; j < 2; ++j) {
                int idx = (((mt0 + mi) * NKT + (2 * n + j)) * 32) + l;
                Ah[mi][j] = g_xah[idx];
                Al[mi][j] = g_xal[idx];
            }

        float acc[2][4][4];
#pragma unroll
        for (int mi = 0; mi < 2; ++mi)
#pragma unroll
            for (int v8i = 0; v8i < 4; ++v8i)
#pragma unroll
                for (int q = 0; q < 4; ++q) acc[mi][v8i][q] = 0.0f;

#pragma unroll
        for (int mi = 0; mi < 2; ++mi)
#pragma unroll
            for (int v8i = 0; v8i < 4; ++v8i)
#pragma unroll
                for (int j = 0; j < 2; ++j) {
                    float* d = acc[mi][v8i];
                    mma16816(d[0], d[1], d[2], d[3], Ah[mi][j], Bh[v8i][j]);
                    mma16816(d[0], d[1], d[2], d[3], Ah[mi][j], Bl[v8i][j]);
                    mma16816(d[0], d[1], d[2], d[3], Al[mi][j], Bh[v8i][j]);
                }

#pragma unroll
        for (int mi = 0; mi < 2; ++mi) {
            const int mlo = (mt0 + mi) * 16 + g;
#pragma unroll
            for (int v8i = 0; v8i < 4; ++v8i) {
                const int v = (bx * 4 + v8i) * 8 + t * 2;
                float* d = acc[mi][v8i];
                st_cs_f2(&logits[((mlo + 0) * NB + n) * VV + v], d[0], d[1]);
                st_cs_f2(&logits[((mlo + 8) * NB + n) * VV + v], d[2], d[3]);
            }
        }
    }
}

// ---------------------------------------------------------------------------
extern "C" void kernel_launch(void* const* d_in, const int* in_sizes, int n_in,
                              void* d_out, int out_size)
{
    const float* h   = (const float*)d_in[0];  // (B,L,768) f32
    const float* age = (const float*)d_in[1];  // (B,L) f32
    const float* ta  = (const float*)d_in[2];  // (B,L) f32 targets_age
    // d_in[3] = delta_t (unused by outputs)
    const int*   tg  = (const int*)d_in[4];    // (B,L) i32 targets
    const float* W1  = (const float*)d_in[5];  // (768,256) f32
    const float* W2  = (const float*)d_in[6];  // (32,1280) f32

    float* out = (float*)d_out;
    float* out_logits = out;                                  // B*L*8*V
    float* out_tte    = out + (size_t)BB * LL * NB * VV;      // B*L*V
    float* out_mask   = out_tte + (size_t)BB * LL * VV;       // B*L*8*V

    fused_prep_kernel<<<NSCAN + NWBLK + NHBLK, 256>>>(W1, W2, h, tg);
    fused_g1_tte_kernel<<<768, 160>>>(tg, age, ta, out_tte, out_mask);
    gemm2_mma_kernel<<<dim3(VV / 32, (BB * LL) / 128), 128>>>(out_logits);
}